// round 16
// baseline (speedup 1.0000x reference)
#include <cuda_runtime.h>
#include <cstdint>

#define NN      8192
#define THREADS 640                   // 20 warps per CTA
#define NCTA    148
#define WPC     (THREADS / 32)        // 20
#define NWARPS  (NCTA * WPC)          // 2960
#define NSEG    32                    // column segments of 256 cols
#define SEGC    256
#define NRG     92                    // rowgroups (32*92 = 2944 working warps)
#define RU      5                     // rows per inner iteration (15 values + pad)
#define RBLKS   128                   // reduce grid: CTA = 64 nodes (quarter segment)

// scratch: __device__ globals (allocation-free rule). Every read slot has
// exactly one unconditional writer per launch; g_done reset by the unique
// last reduce block -> graph-replay deterministic.
__device__ float g_degpart[NWARPS * SEGC];      // 2.9 MB (only w < 2944 read)
__device__ float g_dotpart[NSEG * NN * 3];      // 3.1 MB
__device__ float g_losspart[RBLKS];
__device__ int   g_done;

__device__ __forceinline__ float warp_sum(float v) {
    v += __shfl_down_sync(0xFFFFFFFFu, v, 16);
    v += __shfl_down_sync(0xFFFFFFFFu, v, 8);
    v += __shfl_down_sync(0xFFFFFFFFu, v, 4);
    v += __shfl_down_sync(0xFFFFFFFFu, v, 2);
    v += __shfl_down_sync(0xFFFFFFFFu, v, 1);
    return v;
}

// one butterfly step: live values v[0..L-1] -> v[0..L/2-1], width W
// NOTE: all 32 lanes must be convergent.
template <int L, int W>
__device__ __forceinline__ void bstep(float* v, int lane) {
    const int hi = lane & W;
    #pragma unroll
    for (int j = 0; j < L / 2; j++) {
        const float sent = hi ? v[j] : v[j + L / 2];
        const float got  = __shfl_xor_sync(0xFFFFFFFFu, sent, W);
        v[j] = (hi ? v[j + L / 2] : v[j]) + got;
    }
}

// ---------- kernel A: one streaming pass over A (exact R15 config) ----------
__global__ void __launch_bounds__(THREADS, 1)
spmm_kernel(const float* __restrict__ pred1,
            const float* __restrict__ pred2,
            const float* __restrict__ A) {
    const int tid  = threadIdx.x;
    const int lane = tid & 31;
    const int warp = tid >> 5;

    const int w    = blockIdx.x * WPC + warp;
    const int seg  = w & (NSEG - 1);
    const int rg   = w >> 5;
    const int col0 = seg * SEGC + lane * 8;        // this lane's 8 columns
    const bool active = (rg < NRG);
    const int r0   = active ? (rg * NN) / NRG : 0;
    const int r1   = active ? ((rg + 1) * NN) / NRG : 0;

    // hoist p = pred2 - pred1 for this lane's 8 columns: p[jc][d], 24 regs
    float p[8][3];
    {
        const float4* q1 = reinterpret_cast<const float4*>(pred1 + (size_t)col0 * 3);
        const float4* q2 = reinterpret_cast<const float4*>(pred2 + (size_t)col0 * 3);
        float tmp[24];
        #pragma unroll
        for (int k = 0; k < 6; k++) {
            const float4 a = q2[k];
            const float4 b = q1[k];
            tmp[4 * k + 0] = a.x - b.x;
            tmp[4 * k + 1] = a.y - b.y;
            tmp[4 * k + 2] = a.z - b.z;
            tmp[4 * k + 3] = a.w - b.w;
        }
        #pragma unroll
        for (int j = 0; j < 24; j++) p[j / 3][j % 3] = tmp[j];
    }

    float dg[8];
    #pragma unroll
    for (int j = 0; j < 8; j++) dg[j] = 0.0f;

    const float4* __restrict__ Abase =
        reinterpret_cast<const float4*>(A + (size_t)r0 * NN + col0);
    const int stride4 = NN / 4;
    const int rows = r1 - r0;

    int r = 0;
    for (; r + RU <= rows; r += RU) {
        // front-batch 2*RU = 10 independent loads
        float4 av[RU][2];
        #pragma unroll
        for (int k = 0; k < RU; k++) {
            const float4* rp = Abase + (size_t)(r + k) * stride4;
            av[k][0] = __ldcs(rp);
            av[k][1] = __ldcs(rp + 1);
        }

        float v[16];
        #pragma unroll
        for (int k = 0; k < RU; k++) {
            const float4 a0 = av[k][0], a1 = av[k][1];
            #pragma unroll
            for (int d = 0; d < 3; d++) {
                v[k * 3 + d] =
                    a0.x * p[0][d] + a0.y * p[1][d] + a0.z * p[2][d] + a0.w * p[3][d] +
                    a1.x * p[4][d] + a1.y * p[5][d] + a1.z * p[6][d] + a1.w * p[7][d];
            }
            dg[0] += a0.x; dg[1] += a0.y; dg[2] += a0.z; dg[3] += a0.w;
            dg[4] += a1.x; dg[5] += a1.y; dg[6] += a1.z; dg[7] += a1.w;
        }
        v[15] = 0.0f;                              // pad to 16

        // multi-value butterfly: after 5 steps, lane pair floor(l/2)
        // holds the full 32-lane sum of value floor(l/2)
        bstep<16, 16>(v, lane);
        bstep<8, 8>(v, lane);
        bstep<4, 4>(v, lane);
        bstep<2, 2>(v, lane);
        v[0] += __shfl_xor_sync(0xFFFFFFFFu, v[0], 1);

        const int k = lane >> 1;                   // value index 0..15
        if ((lane & 1) == 0 && k < 15)             // contiguous 60B store
            g_dotpart[((size_t)seg * NN + (r0 + r)) * 3 + k] = v[0];
    }

    // tail rows (<= RU-1): plain warp reductions, fully convergent
    for (; r < rows; r++) {
        const float4* rp = Abase + (size_t)r * stride4;
        const float4 a0 = __ldcs(rp);
        const float4 a1 = __ldcs(rp + 1);
        float t0 = warp_sum(
            a0.x * p[0][0] + a0.y * p[1][0] + a0.z * p[2][0] + a0.w * p[3][0] +
            a1.x * p[4][0] + a1.y * p[5][0] + a1.z * p[6][0] + a1.w * p[7][0]);
        float t1 = warp_sum(
            a0.x * p[0][1] + a0.y * p[1][1] + a0.z * p[2][1] + a0.w * p[3][1] +
            a1.x * p[4][1] + a1.y * p[5][1] + a1.z * p[6][1] + a1.w * p[7][1]);
        float t2 = warp_sum(
            a0.x * p[0][2] + a0.y * p[1][2] + a0.z * p[2][2] + a0.w * p[3][2] +
            a1.x * p[4][2] + a1.y * p[5][2] + a1.z * p[6][2] + a1.w * p[7][2]);
        dg[0] += a0.x; dg[1] += a0.y; dg[2] += a0.z; dg[3] += a0.w;
        dg[4] += a1.x; dg[5] += a1.y; dg[6] += a1.z; dg[7] += a1.w;
        if (lane == 0) {
            float* dst = g_dotpart + ((size_t)seg * NN + (r0 + r)) * 3;
            dst[0] = t0; dst[1] = t1; dst[2] = t2;
        }
    }

    // flush deg partials (coalesced; inactive warps write zeros to unread slot)
    {
        float* dst = g_degpart + (size_t)w * SEGC + lane * 8;
        float4 d0; d0.x = dg[0]; d0.y = dg[1]; d0.z = dg[2]; d0.w = dg[3];
        float4 d1; d1.x = dg[4]; d1.y = dg[5]; d1.z = dg[6]; d1.w = dg[7];
        *reinterpret_cast<float4*>(dst)     = d0;
        *reinterpret_cast<float4*>(dst + 4) = d1;
    }
}

// ---------- kernel B: massively parallel reduce + fused final ----------
// CTA b owns 64 nodes = quarter of segment (b>>2). Flat strided loops with
// coalesced loads and spread smem atomics; latency hidden by 64K threads.
__global__ void __launch_bounds__(512)
reduce_kernel(const float* __restrict__ pred1,
              const float* __restrict__ pred2,
              float* __restrict__ out) {
    __shared__ float sdeg[64];
    __shared__ float sdot[192];
    __shared__ float red[16];
    __shared__ int  isLast;

    const int tid  = threadIdx.x;
    const int lane = tid & 31;
    const int warp = tid >> 5;
    const int b    = blockIdx.x;
    const int s    = b >> 2;                       // segment
    const int cb   = (b & 3) * 64;                 // column base within segment
    const int nbase = b * 64;                      // first node of this CTA

    // zero smem accumulators
    if (tid < 64)  sdeg[tid] = 0.0f;
    if (tid < 192) sdot[tid] = 0.0f;
    __syncthreads();

    // deg: 92 rowgroups x 64 cols = 5888 coalesced loads, spread smem atomics
    {
        const float* base = g_degpart + (size_t)s * SEGC + cb;
        for (int idx = tid; idx < NRG * 64; idx += 512) {
            const int rg = idx >> 6;
            const int c  = idx & 63;
            atomicAdd(&sdeg[c], base[(size_t)rg * (NSEG * SEGC) + c]);
        }
    }
    // dot: 32 segments x 192 contiguous floats = 6144 coalesced loads
    {
        const float* base = g_dotpart + (size_t)nbase * 3;
        for (int idx = tid; idx < NSEG * 192; idx += 512) {
            const int sg = idx / 192;
            const int e  = idx - sg * 192;
            atomicAdd(&sdot[e], base[(size_t)sg * (NN * 3) + e]);
        }
    }
    __syncthreads();

    // per-node loss (64 nodes), block reduce
    float sl = 0.0f;
    if (tid < 64) {
        const int i = nbase + tid;
        const float inv = 1.0f / sdeg[tid];
        const float p0 = pred2[3 * i + 0] - pred1[3 * i + 0];
        const float p1 = pred2[3 * i + 1] - pred1[3 * i + 1];
        const float p2 = pred2[3 * i + 2] - pred1[3 * i + 2];
        const float e0 = p0 - sdot[3 * tid + 0] * inv;
        const float e1 = p1 - sdot[3 * tid + 1] * inv;
        const float e2 = p2 - sdot[3 * tid + 2] * inv;
        sl = e0 * e0 + e1 * e1 + e2 * e2;
    }
    sl = warp_sum(sl);
    if (lane == 0) red[warp] = sl;
    __syncthreads();
    if (tid == 0) {
        float v = red[0] + red[1];                 // only warps 0,1 had nonzero
        g_losspart[b] = v;
        __threadfence();
        isLast = (atomicAdd(&g_done, 1) == RBLKS - 1);
    }
    __syncthreads();

    if (isLast && warp == 0) {
        __threadfence();
        float v = __ldcg(&g_losspart[lane])
                + __ldcg(&g_losspart[lane + 32])
                + __ldcg(&g_losspart[lane + 64])
                + __ldcg(&g_losspart[lane + 96]);
        v = warp_sum(v);
        if (lane == 0) {
            out[0] = v;
            g_done = 0;                            // reset for next replay
        }
    }
}

extern "C" void kernel_launch(void* const* d_in, const int* in_sizes, int n_in,
                              void* d_out, int out_size) {
    const float* pred1 = (const float*)d_in[0];
    const float* pred2 = (const float*)d_in[1];
    const float* A     = (const float*)d_in[2];
    float* out = (float*)d_out;

    spmm_kernel<<<NCTA, THREADS>>>(pred1, pred2, A);
    reduce_kernel<<<RBLKS, 512>>>(pred1, pred2, out);
}

// round 17
// speedup vs baseline: 1.1100x; 1.1100x over previous
#include <cuda_runtime.h>
#include <cstdint>

#define NN      8192
#define THREADS 640                   // 20 warps per CTA
#define NCTA    148
#define WPC     (THREADS / 32)        // 20
#define NWARPS  (NCTA * WPC)          // 2960
#define NSEG    32                    // column segments of 256 cols
#define SEGC    256
#define NRG     92                    // rowgroups (32*92 = 2944 working warps)
#define RU      5                     // rows per inner iteration (15 values + pad)
#define RBLKS   256                   // reduce grid: CTA = 32 nodes (eighth segment)

// scratch: __device__ globals (allocation-free rule). Every read slot has
// exactly one unconditional writer per launch; g_done reset by the unique
// last reduce block -> graph-replay deterministic.
__device__ float g_degpart[NWARPS * SEGC];      // 2.9 MB (only w < 2944 read)
__device__ float g_dotpart[NSEG * NN * 3];      // 3.1 MB
__device__ float g_losspart[RBLKS];
__device__ int   g_done;

__device__ __forceinline__ float warp_sum(float v) {
    v += __shfl_down_sync(0xFFFFFFFFu, v, 16);
    v += __shfl_down_sync(0xFFFFFFFFu, v, 8);
    v += __shfl_down_sync(0xFFFFFFFFu, v, 4);
    v += __shfl_down_sync(0xFFFFFFFFu, v, 2);
    v += __shfl_down_sync(0xFFFFFFFFu, v, 1);
    return v;
}

// one butterfly step: live values v[0..L-1] -> v[0..L/2-1], width W
// NOTE: all 32 lanes must be convergent.
template <int L, int W>
__device__ __forceinline__ void bstep(float* v, int lane) {
    const int hi = lane & W;
    #pragma unroll
    for (int j = 0; j < L / 2; j++) {
        const float sent = hi ? v[j] : v[j + L / 2];
        const float got  = __shfl_xor_sync(0xFFFFFFFFu, sent, W);
        v[j] = (hi ? v[j + L / 2] : v[j]) + got;
    }
}

// ---------- kernel A: one streaming pass over A (exact R15 config) ----------
__global__ void __launch_bounds__(THREADS, 1)
spmm_kernel(const float* __restrict__ pred1,
            const float* __restrict__ pred2,
            const float* __restrict__ A) {
    const int tid  = threadIdx.x;
    const int lane = tid & 31;
    const int warp = tid >> 5;

    const int w    = blockIdx.x * WPC + warp;
    const int seg  = w & (NSEG - 1);
    const int rg   = w >> 5;
    const int col0 = seg * SEGC + lane * 8;        // this lane's 8 columns
    const bool active = (rg < NRG);
    const int r0   = active ? (rg * NN) / NRG : 0;
    const int r1   = active ? ((rg + 1) * NN) / NRG : 0;

    // hoist p = pred2 - pred1 for this lane's 8 columns: p[jc][d], 24 regs
    float p[8][3];
    {
        const float4* q1 = reinterpret_cast<const float4*>(pred1 + (size_t)col0 * 3);
        const float4* q2 = reinterpret_cast<const float4*>(pred2 + (size_t)col0 * 3);
        float tmp[24];
        #pragma unroll
        for (int k = 0; k < 6; k++) {
            const float4 a = q2[k];
            const float4 b = q1[k];
            tmp[4 * k + 0] = a.x - b.x;
            tmp[4 * k + 1] = a.y - b.y;
            tmp[4 * k + 2] = a.z - b.z;
            tmp[4 * k + 3] = a.w - b.w;
        }
        #pragma unroll
        for (int j = 0; j < 24; j++) p[j / 3][j % 3] = tmp[j];
    }

    float dg[8];
    #pragma unroll
    for (int j = 0; j < 8; j++) dg[j] = 0.0f;

    const float4* __restrict__ Abase =
        reinterpret_cast<const float4*>(A + (size_t)r0 * NN + col0);
    const int stride4 = NN / 4;
    const int rows = r1 - r0;

    int r = 0;
    for (; r + RU <= rows; r += RU) {
        // front-batch 2*RU = 10 independent loads
        float4 av[RU][2];
        #pragma unroll
        for (int k = 0; k < RU; k++) {
            const float4* rp = Abase + (size_t)(r + k) * stride4;
            av[k][0] = __ldcs(rp);
            av[k][1] = __ldcs(rp + 1);
        }

        float v[16];
        #pragma unroll
        for (int k = 0; k < RU; k++) {
            const float4 a0 = av[k][0], a1 = av[k][1];
            #pragma unroll
            for (int d = 0; d < 3; d++) {
                v[k * 3 + d] =
                    a0.x * p[0][d] + a0.y * p[1][d] + a0.z * p[2][d] + a0.w * p[3][d] +
                    a1.x * p[4][d] + a1.y * p[5][d] + a1.z * p[6][d] + a1.w * p[7][d];
            }
            dg[0] += a0.x; dg[1] += a0.y; dg[2] += a0.z; dg[3] += a0.w;
            dg[4] += a1.x; dg[5] += a1.y; dg[6] += a1.z; dg[7] += a1.w;
        }
        v[15] = 0.0f;                              // pad to 16

        // multi-value butterfly: after 5 steps, lane pair floor(l/2)
        // holds the full 32-lane sum of value floor(l/2)
        bstep<16, 16>(v, lane);
        bstep<8, 8>(v, lane);
        bstep<4, 4>(v, lane);
        bstep<2, 2>(v, lane);
        v[0] += __shfl_xor_sync(0xFFFFFFFFu, v[0], 1);

        const int k = lane >> 1;                   // value index 0..15
        if ((lane & 1) == 0 && k < 15)             // contiguous 60B store
            g_dotpart[((size_t)seg * NN + (r0 + r)) * 3 + k] = v[0];
    }

    // tail rows (<= RU-1): plain warp reductions, fully convergent
    for (; r < rows; r++) {
        const float4* rp = Abase + (size_t)r * stride4;
        const float4 a0 = __ldcs(rp);
        const float4 a1 = __ldcs(rp + 1);
        float t0 = warp_sum(
            a0.x * p[0][0] + a0.y * p[1][0] + a0.z * p[2][0] + a0.w * p[3][0] +
            a1.x * p[4][0] + a1.y * p[5][0] + a1.z * p[6][0] + a1.w * p[7][0]);
        float t1 = warp_sum(
            a0.x * p[0][1] + a0.y * p[1][1] + a0.z * p[2][1] + a0.w * p[3][1] +
            a1.x * p[4][1] + a1.y * p[5][1] + a1.z * p[6][1] + a1.w * p[7][1]);
        float t2 = warp_sum(
            a0.x * p[0][2] + a0.y * p[1][2] + a0.z * p[2][2] + a0.w * p[3][2] +
            a1.x * p[4][2] + a1.y * p[5][2] + a1.z * p[6][2] + a1.w * p[7][2]);
        dg[0] += a0.x; dg[1] += a0.y; dg[2] += a0.z; dg[3] += a0.w;
        dg[4] += a1.x; dg[5] += a1.y; dg[6] += a1.z; dg[7] += a1.w;
        if (lane == 0) {
            float* dst = g_dotpart + ((size_t)seg * NN + (r0 + r)) * 3;
            dst[0] = t0; dst[1] = t1; dst[2] = t2;
        }
    }

    // flush deg partials (coalesced; inactive warps write zeros to unread slot)
    {
        float* dst = g_degpart + (size_t)w * SEGC + lane * 8;
        float4 d0; d0.x = dg[0]; d0.y = dg[1]; d0.z = dg[2]; d0.w = dg[3];
        float4 d1; d1.x = dg[4]; d1.y = dg[5]; d1.z = dg[6]; d1.w = dg[7];
        *reinterpret_cast<float4*>(dst)     = d0;
        *reinterpret_cast<float4*>(dst + 4) = d1;
    }
}

// ---------- kernel B: coalesced, contention-free, parallel reduce ----------
// CTA b owns 32 nodes = eighth of segment (b>>3). All loads coalesced, all
// accumulation in registers + plain smem stores (no atomics anywhere).
__global__ void __launch_bounds__(256)
reduce_kernel(const float* __restrict__ pred1,
              const float* __restrict__ pred2,
              float* __restrict__ out) {
    __shared__ float sdeg2[256];       // [grp8][col32]
    __shared__ float sdot2[768];       // [segquad8][elem96]
    __shared__ float sdeg[32];
    __shared__ float sdot[96];
    __shared__ float red[8];
    __shared__ int  isLast;

    const int tid  = threadIdx.x;
    const int lane = tid & 31;
    const int warp = tid >> 5;
    const int b    = blockIdx.x;
    const int s    = b >> 3;                       // segment
    const int cb   = (b & 7) * 32;                 // column base within segment
    const int nbase = b * 32;                      // first node of this CTA

    // deg partials: group grp covers rowgroups [grp*NRG/8, (grp+1)*NRG/8)
    {
        const int c   = tid & 31;
        const int grp = tid >> 5;
        const int rg0 = (grp * NRG) / 8;
        const int rg1 = ((grp + 1) * NRG) / 8;     // 11 or 12 iters
        const float* base = g_degpart + (size_t)s * SEGC + cb + c;
        float acc = 0.0f;
        #pragma unroll 4
        for (int rg = rg0; rg < rg1; rg++)
            acc += base[(size_t)rg * (NSEG * SEGC)];
        sdeg2[tid] = acc;
    }

    // dot partials: slot idx = (segquad q, elem e); q sums 4 segments of the
    // CTA's 96 contiguous floats (nodes nbase..nbase+31, dims interleaved)
    {
        const float* base = g_dotpart + (size_t)nbase * 3;
        #pragma unroll
        for (int idx = tid; idx < 768; idx += 256) {
            const int q = idx / 96;
            const int e = idx - q * 96;
            float acc = 0.0f;
            #pragma unroll
            for (int k = 0; k < 4; k++)
                acc += base[(size_t)(q * 4 + k) * (NN * 3) + e];
            sdot2[idx] = acc;
        }
    }
    __syncthreads();

    if (tid < 32) {
        float acc = 0.0f;
        #pragma unroll
        for (int g = 0; g < 8; g++) acc += sdeg2[g * 32 + tid];
        sdeg[tid] = acc;
    }
    if (tid < 96) {
        float acc = 0.0f;
        #pragma unroll
        for (int g = 0; g < 8; g++) acc += sdot2[g * 96 + tid];
        sdot[tid] = acc;
    }
    __syncthreads();

    // per-node loss (32 nodes), block partial
    float sl = 0.0f;
    if (tid < 32) {
        const int i = nbase + tid;
        const float inv = 1.0f / sdeg[tid];
        const float p0 = pred2[3 * i + 0] - pred1[3 * i + 0];
        const float p1 = pred2[3 * i + 1] - pred1[3 * i + 1];
        const float p2 = pred2[3 * i + 2] - pred1[3 * i + 2];
        const float e0 = p0 - sdot[3 * tid + 0] * inv;
        const float e1 = p1 - sdot[3 * tid + 1] * inv;
        const float e2 = p2 - sdot[3 * tid + 2] * inv;
        sl = e0 * e0 + e1 * e1 + e2 * e2;
    }
    sl = warp_sum(sl);
    if (tid == 0) {
        g_losspart[b] = sl;
        __threadfence();
        isLast = (atomicAdd(&g_done, 1) == RBLKS - 1);
    }
    __syncthreads();

    if (isLast && warp == 0) {
        __threadfence();
        float v = 0.0f;
        #pragma unroll
        for (int k = 0; k < 8; k++)
            v += __ldcg(&g_losspart[lane + 32 * k]);
        v = warp_sum(v);
        if (lane == 0) {
            out[0] = v;
            g_done = 0;                            // reset for next replay
        }
    }
}

extern "C" void kernel_launch(void* const* d_in, const int* in_sizes, int n_in,
                              void* d_out, int out_size) {
    const float* pred1 = (const float*)d_in[0];
    const float* pred2 = (const float*)d_in[1];
    const float* A     = (const float*)d_in[2];
    float* out = (float*)d_out;

    spmm_kernel<<<NCTA, THREADS>>>(pred1, pred2, A);
    reduce_kernel<<<RBLKS, 256>>>(pred1, pred2, out);
}